// round 3
// baseline (speedup 1.0000x reference)
#include <cuda_runtime.h>
#include <cuda_bf16.h>
#include <cstddef>

// Problem constants
#define BATCH 8
#define NSEQ  1032          // 32*32 + 8
#define CDIM  768
#define HEADS 12
#define HD    64
#define MROWS (BATCH*NSEQ)  // 8256
#define KVW   1536          // k+v columns

// Device scratch (static globals — no runtime allocation).
// NOTE: referenced ONLY inside device code (passing a __device__ symbol as a
// host-side kernel argument yields the host shadow address — round-2 bug).
__device__ float g_kv[(size_t)MROWS * KVW];    // [b*N + n][o], o<768 -> K(h*64+d), o>=768 -> V
__device__ float g_att[(size_t)MROWS * CDIM];  // attention output before proj

// ---------------------------------------------------------------------------
// Generic fp32 GEMM: C[m][n] = sum_k A[m][k] * W[(n+woff)][k] + bias[n+woff]
// 128x128 tile, BK=8, 256 threads, 8x8 micro-tile per thread.
// ---------------------------------------------------------------------------
__device__ __forceinline__ void gemm_body(
    const float* __restrict__ A, const float* __restrict__ W,
    const float* __restrict__ bias, float* __restrict__ C,
    int M, int N, int K, int woff)
{
    __shared__ float As[8][128];
    __shared__ float Bs[8][128];
    const int bm = blockIdx.y * 128;
    const int bn = blockIdx.x * 128;
    const int tid = threadIdx.x;
    const int tx = tid & 15;
    const int ty = tid >> 4;

    float acc[8][8];
#pragma unroll
    for (int i = 0; i < 8; i++)
#pragma unroll
        for (int j = 0; j < 8; j++) acc[i][j] = 0.0f;

    const int lr = tid >> 1;        // 0..127
    const int lc = (tid & 1) * 4;   // 0 or 4

    for (int k0 = 0; k0 < K; k0 += 8) {
        float4 a4 = make_float4(0.f, 0.f, 0.f, 0.f);
        float4 b4 = make_float4(0.f, 0.f, 0.f, 0.f);
        const int gm = bm + lr;
        if (gm < M) a4 = *(const float4*)(A + (size_t)gm * K + k0 + lc);
        const int gn = bn + lr;
        if (gn < N) b4 = *(const float4*)(W + (size_t)(gn + woff) * K + k0 + lc);
        As[lc + 0][lr] = a4.x; As[lc + 1][lr] = a4.y;
        As[lc + 2][lr] = a4.z; As[lc + 3][lr] = a4.w;
        Bs[lc + 0][lr] = b4.x; Bs[lc + 1][lr] = b4.y;
        Bs[lc + 2][lr] = b4.z; Bs[lc + 3][lr] = b4.w;
        __syncthreads();

#pragma unroll
        for (int kk = 0; kk < 8; kk++) {
            float4 a0 = *(const float4*)&As[kk][ty * 4];
            float4 a1 = *(const float4*)&As[kk][64 + ty * 4];
            float4 b0 = *(const float4*)&Bs[kk][tx * 4];
            float4 b1 = *(const float4*)&Bs[kk][64 + tx * 4];
            float a[8] = {a0.x, a0.y, a0.z, a0.w, a1.x, a1.y, a1.z, a1.w};
            float b[8] = {b0.x, b0.y, b0.z, b0.w, b1.x, b1.y, b1.z, b1.w};
#pragma unroll
            for (int i = 0; i < 8; i++)
#pragma unroll
                for (int j = 0; j < 8; j++) acc[i][j] += a[i] * b[j];
        }
        __syncthreads();
    }

#pragma unroll
    for (int i = 0; i < 8; i++) {
        const int r = bm + ((i < 4) ? (ty * 4 + i) : (64 + ty * 4 + (i - 4)));
        if (r >= M) continue;
#pragma unroll
        for (int j = 0; j < 8; j++) {
            const int c = bn + ((j < 4) ? (tx * 4 + j) : (64 + tx * 4 + (j - 4)));
            if (c < N) C[(size_t)r * N + c] = acc[i][j] + bias[c + woff];
        }
    }
}

__global__ __launch_bounds__(256) void gemm_kv_kernel(
    const float* __restrict__ x, const float* __restrict__ qkv_w,
    const float* __restrict__ qkv_b)
{
    // Only K and V thirds of qkv: weight rows [768, 2304)
    gemm_body(x, qkv_w, qkv_b, g_kv, MROWS, KVW, CDIM, CDIM);
}

__global__ __launch_bounds__(256) void gemm_proj_kernel(
    const float* __restrict__ proj_w, const float* __restrict__ proj_b,
    float* __restrict__ out)
{
    gemm_body(g_att, proj_w, proj_b, out, MROWS, CDIM, CDIM, 0);
}

// ---------------------------------------------------------------------------
// Fused attention: per block = one (b,h) and an 8-row i-tile.
// attn[b,h,i,j] = (k_i . k_j)*scale + gauss(i,j); softmax over j; @ V.
// gauss(i,j) = f(di)*f(dl), f(x)=exp(-x^2/50), zero on prefix rows/cols.
// Writes g_att directly (device-side symbol reference).
// ---------------------------------------------------------------------------
__global__ __launch_bounds__(256) void attn_kernel()
{
    __shared__ float ks[8][64];       // k rows of this i-tile (reused as reduction buf)
    __shared__ float p[8][NSEQ];      // logits -> probabilities (unnormalized)
    __shared__ float ftab[63];
    __shared__ float invs[8];

    const int tid = threadIdx.x;
    const int bh = blockIdx.y;
    const int b = bh / HEADS, h = bh % HEADS;
    const int i0 = blockIdx.x * 8;

    const float* Kp = g_kv + (size_t)b * NSEQ * KVW + h * HD;   // k[b][j][h*64+d] = Kp[j*1536+d]
    const float* Vp = Kp + CDIM;                                // v at +768

    if (tid < 63) {
        float xx = (float)tid - 31.0f;
        ftab[tid] = __expf(-xx * xx * (1.0f / 50.0f));
    }
    for (int idx = tid; idx < 512; idx += 256) {
        int r = idx >> 6, d = idx & 63;
        ks[r][d] = Kp[(size_t)(i0 + r) * KVW + d];
    }
    __syncthreads();

    const float scale = 0.125f;   // hd^-0.5

    // ---- phase 2: logits. Each thread owns 4 j's: tid, tid+256, tid+512, tid+768.
    {
        int qi1[8], qi2[8];
#pragma unroll
        for (int r = 0; r < 8; r++) {
            int i = i0 + r;
            qi1[r] = (i - 8) >> 5;
            qi2[r] = (i - 8) & 31;
        }

        float acc[4][8];
#pragma unroll
        for (int s = 0; s < 4; s++)
#pragma unroll
            for (int r = 0; r < 8; r++) acc[s][r] = 0.0f;

        const float* kp0 = Kp + (size_t)tid * KVW;
        const float* kp1 = Kp + (size_t)(tid + 256) * KVW;
        const float* kp2 = Kp + (size_t)(tid + 512) * KVW;
        const float* kp3 = Kp + (size_t)(tid + 768) * KVW;

#pragma unroll
        for (int d4 = 0; d4 < 16; d4++) {
            float4 kj0 = *(const float4*)(kp0 + d4 * 4);
            float4 kj1 = *(const float4*)(kp1 + d4 * 4);
            float4 kj2 = *(const float4*)(kp2 + d4 * 4);
            float4 kj3 = *(const float4*)(kp3 + d4 * 4);
#pragma unroll
            for (int r = 0; r < 8; r++) {
                float4 kr = *(const float4*)&ks[r][d4 * 4];
                acc[0][r] += kr.x * kj0.x + kr.y * kj0.y + kr.z * kj0.z + kr.w * kj0.w;
                acc[1][r] += kr.x * kj1.x + kr.y * kj1.y + kr.z * kj1.z + kr.w * kj1.w;
                acc[2][r] += kr.x * kj2.x + kr.y * kj2.y + kr.z * kj2.z + kr.w * kj2.w;
                acc[3][r] += kr.x * kj3.x + kr.y * kj3.y + kr.z * kj3.z + kr.w * kj3.w;
            }
        }

#pragma unroll
        for (int s = 0; s < 4; s++) {
            int j = tid + 256 * s;
            int kj1 = (j - 8) >> 5, kj2 = (j - 8) & 31;
#pragma unroll
            for (int r = 0; r < 8; r++) {
                float addv = 0.0f;
                if (j >= 8 && (i0 + r) >= 8)
                    addv = ftab[qi1[r] - kj1 + 31] * ftab[qi2[r] - kj2 + 31];
                p[r][j] = acc[s][r] * scale + addv;
            }
        }
    }

    // remainder j in [1024, 1032)
    if (tid < 8) {
        int j = 1024 + tid;
        const float* kpj = Kp + (size_t)j * KVW;
        float acc[8];
#pragma unroll
        for (int r = 0; r < 8; r++) acc[r] = 0.0f;
#pragma unroll
        for (int d4 = 0; d4 < 16; d4++) {
            float4 kj = *(const float4*)(kpj + d4 * 4);
#pragma unroll
            for (int r = 0; r < 8; r++) {
                float4 kr = *(const float4*)&ks[r][d4 * 4];
                acc[r] += kr.x * kj.x + kr.y * kj.y + kr.z * kj.z + kr.w * kj.w;
            }
        }
        int kj1 = (j - 8) >> 5, kj2 = (j - 8) & 31;
#pragma unroll
        for (int r = 0; r < 8; r++) {
            int i = i0 + r;
            float addv = 0.0f;
            if (i >= 8) {
                int d1 = ((i - 8) >> 5) - kj1, d2 = ((i - 8) & 31) - kj2;
                addv = ftab[d1 + 31] * ftab[d2 + 31];
            }
            p[r][j] = acc[r] * scale + addv;
        }
    }
    __syncthreads();

    // ---- phase 3: softmax, one warp per row
    {
        const int w = tid >> 5, lane = tid & 31;
        float m = -1e30f;
        for (int j = lane; j < NSEQ; j += 32) m = fmaxf(m, p[w][j]);
#pragma unroll
        for (int o = 16; o; o >>= 1) m = fmaxf(m, __shfl_xor_sync(0xffffffffu, m, o));
        float s = 0.0f;
        for (int j = lane; j < NSEQ; j += 32) {
            float e = __expf(p[w][j] - m);
            p[w][j] = e;
            s += e;
        }
#pragma unroll
        for (int o = 16; o; o >>= 1) s += __shfl_xor_sync(0xffffffffu, s, o);
        if (lane == 0) invs[w] = 1.0f / s;
    }
    __syncthreads();

    // ---- phase 4: out[i,d] = sum_j p[i][j] * v[j][d], split j over 2 halves
    {
        float* red = &ks[0][0];        // 512-float reduction buffer (ks no longer needed)
        const int half = tid >> 7;     // j parity
        const int tt = tid & 127;
        const int r = tt >> 4;         // 0..7
        const int d = (tt & 15) * 4;

        float4 acc = make_float4(0.f, 0.f, 0.f, 0.f);
        for (int j = half; j < NSEQ; j += 2) {
            float4 v4 = *(const float4*)(Vp + (size_t)j * KVW + d);
            float pv = p[r][j];
            acc.x += pv * v4.x;
            acc.y += pv * v4.y;
            acc.z += pv * v4.z;
            acc.w += pv * v4.w;
        }
        if (half == 1) *(float4*)&red[tt * 4] = acc;
        __syncthreads();
        if (half == 0) {
            float4 o2 = *(const float4*)&red[tt * 4];
            float inv = invs[r];
            float4 o;
            o.x = (acc.x + o2.x) * inv;
            o.y = (acc.y + o2.y) * inv;
            o.z = (acc.z + o2.z) * inv;
            o.w = (acc.w + o2.w) * inv;
            *(float4*)(g_att + ((size_t)(b * NSEQ + i0 + r)) * CDIM + h * HD + d) = o;
        }
    }
}

// ---------------------------------------------------------------------------
extern "C" void kernel_launch(void* const* d_in, const int* in_sizes, int n_in,
                              void* d_out, int out_size)
{
    // Dispatch inputs by element count (robust to metadata ordering):
    // x: 6340608, qkv_w: 1769472, qkv_b: 2304, proj_w: 589824, proj_b: 768
    const float* x = nullptr;
    const float* qkv_w = nullptr;
    const float* qkv_b = nullptr;
    const float* proj_w = nullptr;
    const float* proj_b = nullptr;
    for (int i = 0; i < n_in; i++) {
        switch (in_sizes[i]) {
            case 6340608: x      = (const float*)d_in[i]; break;
            case 1769472: qkv_w  = (const float*)d_in[i]; break;
            case 2304:    qkv_b  = (const float*)d_in[i]; break;
            case 589824:  proj_w = (const float*)d_in[i]; break;
            case 768:     proj_b = (const float*)d_in[i]; break;
        }
    }
    float* out = (float*)d_out;

    // 1) K,V projection: [8256,768] x [1536,768]^T -> g_kv
    {
        dim3 grid(KVW / 128, (MROWS + 127) / 128);   // 12 x 65
        gemm_kv_kernel<<<grid, 256>>>(x, qkv_w, qkv_b);
    }
    // 2) fused gaussian-bias attention -> g_att
    {
        dim3 grid(NSEQ / 8, BATCH * HEADS);          // 129 x 96
        attn_kernel<<<grid, 256>>>();
    }
    // 3) output projection -> d_out
    {
        dim3 grid(CDIM / 128, (MROWS + 127) / 128);  // 6 x 65
        gemm_proj_kernel<<<grid, 256>>>(proj_w, proj_b, out);
    }
}

// round 6
// speedup vs baseline: 2.2918x; 2.2918x over previous
#include <cuda_runtime.h>
#include <cuda_bf16.h>
#include <cstddef>

// Problem constants
#define BATCH 8
#define NSEQ  1032          // 32*32 + 8
#define CDIM  768
#define HEADS 12
#define HD    64
#define MROWS (BATCH*NSEQ)  // 8256
#define KVW   1536          // k+v columns

// Device scratch (static globals — no runtime allocation).
// Referenced ONLY inside device code.
__device__ float g_kv[(size_t)MROWS * KVW];    // [b*N + n][o], o<768 -> K(h*64+d), o>=768 -> V
__device__ float g_att[(size_t)MROWS * CDIM];  // attention output before proj

// ---------------------------------------------------------------------------
// fp32 GEMM: C[m][n] = sum_k A[m][k] * W[(n+woff)][k] + bias[n+woff]
// 128x128 tile, BK=8, 256 threads, 8x8 micro-tile per thread.
// ---------------------------------------------------------------------------
__device__ __forceinline__ void gemm_body(
    const float* __restrict__ A, const float* __restrict__ W,
    const float* __restrict__ bias, float* __restrict__ C,
    int M, int N, int K, int woff)
{
    __shared__ float As[8][128];
    __shared__ float Bs[8][128];
    const int bm = blockIdx.y * 128;
    const int bn = blockIdx.x * 128;
    const int tid = threadIdx.x;
    const int tx = tid & 15;
    const int ty = tid >> 4;

    float acc[8][8];
#pragma unroll
    for (int i = 0; i < 8; i++)
#pragma unroll
        for (int j = 0; j < 8; j++) acc[i][j] = 0.0f;

    const int lr = tid >> 1;
    const int lc = (tid & 1) * 4;

    for (int k0 = 0; k0 < K; k0 += 8) {
        float4 a4 = make_float4(0.f, 0.f, 0.f, 0.f);
        float4 b4 = make_float4(0.f, 0.f, 0.f, 0.f);
        const int gm = bm + lr;
        if (gm < M) a4 = *(const float4*)(A + (size_t)gm * K + k0 + lc);
        const int gn = bn + lr;
        if (gn < N) b4 = *(const float4*)(W + (size_t)(gn + woff) * K + k0 + lc);
        As[lc + 0][lr] = a4.x; As[lc + 1][lr] = a4.y;
        As[lc + 2][lr] = a4.z; As[lc + 3][lr] = a4.w;
        Bs[lc + 0][lr] = b4.x; Bs[lc + 1][lr] = b4.y;
        Bs[lc + 2][lr] = b4.z; Bs[lc + 3][lr] = b4.w;
        __syncthreads();

#pragma unroll
        for (int kk = 0; kk < 8; kk++) {
            float4 a0 = *(const float4*)&As[kk][ty * 4];
            float4 a1 = *(const float4*)&As[kk][64 + ty * 4];
            float4 b0 = *(const float4*)&Bs[kk][tx * 4];
            float4 b1 = *(const float4*)&Bs[kk][64 + tx * 4];
            float a[8] = {a0.x, a0.y, a0.z, a0.w, a1.x, a1.y, a1.z, a1.w};
            float b[8] = {b0.x, b0.y, b0.z, b0.w, b1.x, b1.y, b1.z, b1.w};
#pragma unroll
            for (int i = 0; i < 8; i++)
#pragma unroll
                for (int j = 0; j < 8; j++) acc[i][j] += a[i] * b[j];
        }
        __syncthreads();
    }

#pragma unroll
    for (int i = 0; i < 8; i++) {
        const int r = bm + ((i < 4) ? (ty * 4 + i) : (64 + ty * 4 + (i - 4)));
        if (r >= M) continue;
#pragma unroll
        for (int j = 0; j < 8; j++) {
            const int c = bn + ((j < 4) ? (tx * 4 + j) : (64 + tx * 4 + (j - 4)));
            if (c < N) C[(size_t)r * N + c] = acc[i][j] + bias[c + woff];
        }
    }
}

__global__ __launch_bounds__(256) void gemm_kv_kernel(
    const float* __restrict__ x, const float* __restrict__ qkv_w,
    const float* __restrict__ qkv_b)
{
    gemm_body(x, qkv_w, qkv_b, g_kv, MROWS, KVW, CDIM, CDIM);
}

__global__ __launch_bounds__(256) void gemm_proj_kernel(
    const float* __restrict__ proj_w, const float* __restrict__ proj_b,
    float* __restrict__ out)
{
    gemm_body(g_att, proj_w, proj_b, out, MROWS, CDIM, CDIM, 0);
}

// ---------------------------------------------------------------------------
// Flash-style fused attention.
// Block = 256 threads, one (b,h), 64 i-rows. Loop over 64-wide j-tiles:
//   S = Ki . Kj^T  (64x64x64 reg-blocked GEMM, 4x4 micro-tile)
//   S = S*scale + gauss bias (separable 63-entry table)
//   online softmax (row stats via shfl width 16)
//   O += P . Vj    (64x64x64 reg-blocked GEMM)
// Dynamic smem: Ki[64][64], KjT[64][68], V[64][68], P[64][68], ftab[64]
// ---------------------------------------------------------------------------
#define ATT_SMEM_FLOATS (64*64 + 3*64*68 + 64)
#define ATT_SMEM_BYTES  (ATT_SMEM_FLOATS * 4)

__global__ __launch_bounds__(256) void attn_kernel()
{
    extern __shared__ float sm[];
    float* Ki_s = sm;                    // [64][64]  stride 64
    float* KjT  = Ki_s + 64 * 64;        // [64][68]  [d][j]
    float* V_s  = KjT  + 64 * 68;        // [64][68]  [j][d]
    float* P_s  = V_s  + 64 * 68;        // [64][68]  [i][j]
    float* ftab = P_s  + 64 * 68;        // [64]

    const int tid = threadIdx.x;
    const int tx = tid & 15;             // j/d micro-col group
    const int ty = tid >> 4;             // i micro-row group
    const int b = blockIdx.y / HEADS, h = blockIdx.y % HEADS;
    const int i0 = blockIdx.x * 64;

    const float* Kp = g_kv + (size_t)b * NSEQ * KVW + h * HD;
    const float* Vp = Kp + CDIM;

    if (tid < 63) {
        float xx = (float)tid - 31.0f;
        ftab[tid] = __expf(-xx * xx * 0.02f);   // f(x)=exp(-x^2/50)
    }

    // Load Ki tile [64][64] (clamp rows past end; those rows are never written out)
    {
        const int i  = tid & 63;
        const int d0 = (tid >> 6) * 16;
        int gi = i0 + i; if (gi > NSEQ - 1) gi = NSEQ - 1;
        const float* src = Kp + (size_t)gi * KVW + d0;
#pragma unroll
        for (int g = 0; g < 4; g++)
            *(float4*)&Ki_s[i * 64 + d0 + 4 * g] = *(const float4*)(src + 4 * g);
    }

    // Per-thread row (i) bias indices.
    // qok MUST exclude phantom rows (i >= NSEQ): their qi1 would reach 33 and
    // overflow ftab (the round-4 IMA).
    int qi1[4], qi2[4]; bool qok[4];
#pragma unroll
    for (int a = 0; a < 4; a++) {
        int i = i0 + ty * 4 + a;
        qok[a] = (i >= 8) && (i < NSEQ);
        qi1[a] = (i - 8) >> 5;
        qi2[a] = (i - 8) & 31;
    }

    float m[4], l[4], O[4][4];
#pragma unroll
    for (int a = 0; a < 4; a++) {
        m[a] = -1e30f; l[a] = 0.0f;
#pragma unroll
        for (int bb = 0; bb < 4; bb++) O[a][bb] = 0.0f;
    }

    const float scale = 0.125f;   // hd^-0.5

    for (int j0 = 0; j0 < NSEQ; j0 += 64) {
        __syncthreads();   // previous tile fully consumed before overwrite

        // Load Kj (transposed -> KjT[d][j]) and Vj (natural -> V_s[j][d])
        {
            const int j  = tid & 63;
            const int d0 = (tid >> 6) * 16;
            int gj = j0 + j; if (gj > NSEQ - 1) gj = NSEQ - 1;
            const float* kc = Kp + (size_t)gj * KVW + d0;
            const float* vc = Vp + (size_t)gj * KVW + d0;
#pragma unroll
            for (int g = 0; g < 4; g++) {
                float4 k4 = *(const float4*)(kc + 4 * g);
                KjT[(d0 + 4 * g + 0) * 68 + j] = k4.x;
                KjT[(d0 + 4 * g + 1) * 68 + j] = k4.y;
                KjT[(d0 + 4 * g + 2) * 68 + j] = k4.z;
                KjT[(d0 + 4 * g + 3) * 68 + j] = k4.w;
                *(float4*)&V_s[j * 68 + d0 + 4 * g] = *(const float4*)(vc + 4 * g);
            }
        }
        __syncthreads();

        // ---- S = Ki . Kj^T (4x4 per thread) ----
        float s[4][4];
#pragma unroll
        for (int a = 0; a < 4; a++)
#pragma unroll
            for (int bb = 0; bb < 4; bb++) s[a][bb] = 0.0f;

#pragma unroll 8
        for (int dd = 0; dd < 64; dd++) {
            float4 kj = *(const float4*)&KjT[dd * 68 + tx * 4];
            float ka0 = Ki_s[(ty * 4 + 0) * 64 + dd];
            float ka1 = Ki_s[(ty * 4 + 1) * 64 + dd];
            float ka2 = Ki_s[(ty * 4 + 2) * 64 + dd];
            float ka3 = Ki_s[(ty * 4 + 3) * 64 + dd];
            s[0][0] += ka0 * kj.x; s[0][1] += ka0 * kj.y; s[0][2] += ka0 * kj.z; s[0][3] += ka0 * kj.w;
            s[1][0] += ka1 * kj.x; s[1][1] += ka1 * kj.y; s[1][2] += ka1 * kj.z; s[1][3] += ka1 * kj.w;
            s[2][0] += ka2 * kj.x; s[2][1] += ka2 * kj.y; s[2][2] += ka2 * kj.z; s[2][3] += ka2 * kj.w;
            s[3][0] += ka3 * kj.x; s[3][1] += ka3 * kj.y; s[3][2] += ka3 * kj.z; s[3][3] += ka3 * kj.w;
        }

        // ---- scale + separable gaussian bias + tail mask ----
#pragma unroll
        for (int bb = 0; bb < 4; bb++) {
            int j = j0 + tx * 4 + bb;
            bool jin = (j < NSEQ);
            bool jbias = jin && (j >= 8);
            int kj1 = (j - 8) >> 5, kj2 = (j - 8) & 31;
#pragma unroll
            for (int a = 0; a < 4; a++) {
                float val = s[a][bb] * scale;
                if (jbias && qok[a])
                    val += ftab[qi1[a] - kj1 + 31] * ftab[qi2[a] - kj2 + 31];
                if (!jin) val = -1e30f;
                s[a][bb] = val;
            }
        }

        // ---- online softmax update + stage P ----
#pragma unroll
        for (int a = 0; a < 4; a++) {
            float tm = fmaxf(fmaxf(s[a][0], s[a][1]), fmaxf(s[a][2], s[a][3]));
#pragma unroll
            for (int o = 8; o; o >>= 1)
                tm = fmaxf(tm, __shfl_xor_sync(0xffffffffu, tm, o, 16));
            float mn = fmaxf(m[a], tm);
            float c = __expf(m[a] - mn);
            float e0 = __expf(s[a][0] - mn);
            float e1 = __expf(s[a][1] - mn);
            float e2 = __expf(s[a][2] - mn);
            float e3 = __expf(s[a][3] - mn);
            float rs = e0 + e1 + e2 + e3;
#pragma unroll
            for (int o = 8; o; o >>= 1)
                rs += __shfl_xor_sync(0xffffffffu, rs, o, 16);
            l[a] = l[a] * c + rs;
            m[a] = mn;
            O[a][0] *= c; O[a][1] *= c; O[a][2] *= c; O[a][3] *= c;
            *(float4*)&P_s[(ty * 4 + a) * 68 + tx * 4] = make_float4(e0, e1, e2, e3);
        }
        __syncthreads();

        // ---- O += P . Vj (4x4 per thread; rows ty*4+a, cols d = tx*4..) ----
#pragma unroll 8
        for (int jj = 0; jj < 64; jj++) {
            float4 v = *(const float4*)&V_s[jj * 68 + tx * 4];
            float p0 = P_s[(ty * 4 + 0) * 68 + jj];
            float p1 = P_s[(ty * 4 + 1) * 68 + jj];
            float p2 = P_s[(ty * 4 + 2) * 68 + jj];
            float p3 = P_s[(ty * 4 + 3) * 68 + jj];
            O[0][0] += p0 * v.x; O[0][1] += p0 * v.y; O[0][2] += p0 * v.z; O[0][3] += p0 * v.w;
            O[1][0] += p1 * v.x; O[1][1] += p1 * v.y; O[1][2] += p1 * v.z; O[1][3] += p1 * v.w;
            O[2][0] += p2 * v.x; O[2][1] += p2 * v.y; O[2][2] += p2 * v.z; O[2][3] += p2 * v.w;
            O[3][0] += p3 * v.x; O[3][1] += p3 * v.y; O[3][2] += p3 * v.z; O[3][3] += p3 * v.w;
        }
    }

    // ---- epilogue: normalize and write ----
#pragma unroll
    for (int a = 0; a < 4; a++) {
        int i = i0 + ty * 4 + a;
        if (i < NSEQ) {
            float inv = 1.0f / l[a];
            float4 o = make_float4(O[a][0] * inv, O[a][1] * inv,
                                   O[a][2] * inv, O[a][3] * inv);
            *(float4*)(g_att + (size_t)(b * NSEQ + i) * CDIM + h * HD + tx * 4) = o;
        }
    }
}

// ---------------------------------------------------------------------------
extern "C" void kernel_launch(void* const* d_in, const int* in_sizes, int n_in,
                              void* d_out, int out_size)
{
    // Dispatch inputs by element count (robust to metadata ordering):
    const float* x = nullptr;
    const float* qkv_w = nullptr;
    const float* qkv_b = nullptr;
    const float* proj_w = nullptr;
    const float* proj_b = nullptr;
    for (int i = 0; i < n_in; i++) {
        switch (in_sizes[i]) {
            case 6340608: x      = (const float*)d_in[i]; break;
            case 1769472: qkv_w  = (const float*)d_in[i]; break;
            case 2304:    qkv_b  = (const float*)d_in[i]; break;
            case 589824:  proj_w = (const float*)d_in[i]; break;
            case 768:     proj_b = (const float*)d_in[i]; break;
        }
    }
    float* out = (float*)d_out;

    // Unconditional (idempotent, not a stream op — capture-safe, no static guard)
    cudaFuncSetAttribute(attn_kernel,
                         cudaFuncAttributeMaxDynamicSharedMemorySize,
                         ATT_SMEM_BYTES);

    // 1) K,V projection: [8256,768] x [1536,768]^T -> g_kv
    {
        dim3 grid(KVW / 128, (MROWS + 127) / 128);   // 12 x 65
        gemm_kv_kernel<<<grid, 256>>>(x, qkv_w, qkv_b);
    }
    // 2) flash-style fused attention -> g_att
    {
        dim3 grid((NSEQ + 63) / 64, BATCH * HEADS);  // 17 x 96
        attn_kernel<<<grid, 256, ATT_SMEM_BYTES>>>();
    }
    // 3) output projection -> d_out
    {
        dim3 grid(CDIM / 128, (MROWS + 127) / 128);  // 6 x 65
        gemm_proj_kernel<<<grid, 256>>>(proj_w, proj_b, out);
    }
}

// round 9
// speedup vs baseline: 3.0932x; 1.3497x over previous
#include <cuda_runtime.h>
#include <cuda_bf16.h>
#include <cstdint>
#include <cstddef>

// Problem constants
#define BATCH 8
#define NSEQ  1032          // 32*32 + 8
#define CDIM  768
#define HEADS 12
#define HD    64
#define MROWS (BATCH*NSEQ)  // 8256
#define KVW   1536          // k+v columns
#define K2    2304          // triple-block K (3*768): A=[hi|hi|lo], B=[hi|lo|hi]

// Device scratch (static globals — no runtime allocation). Referenced ONLY in device code.
__device__ float g_kv[(size_t)MROWS * KVW];          // K|V fp32, consumed by attn
__device__ float g_att[(size_t)MROWS * CDIM];        // attention output fp32
__device__ __nv_bfloat16 g_xc  [(size_t)MROWS * K2]; // x       as A-type: [hi|hi|lo]
__device__ __nv_bfloat16 g_attc[(size_t)MROWS * K2]; // attnout as A-type: [hi|hi|lo]
__device__ __nv_bfloat16 g_wkv [(size_t)KVW   * K2]; // qkv_w rows 768..2303 as B-type: [hi|lo|hi]
__device__ __nv_bfloat16 g_wprj[(size_t)CDIM  * K2]; // proj_w as B-type: [hi|lo|hi]

// ---------------------------------------------------------------------------
// Helpers (portable PTX only: ldmatrix / mma.sync / cp.async — no tcgen05)
// ---------------------------------------------------------------------------
__device__ __forceinline__ uint32_t smem_u32(const void* p) {
    uint32_t a;
    asm("{ .reg .u64 t; cvta.to.shared.u64 t, %1; cvt.u32.u64 %0, t; }" : "=r"(a) : "l"(p));
    return a;
}
#define SMEM_SWIZZLE_128B(x) ((x) ^ (((x) >> 3) & 0x70))

#define CP_ASYNC16(sa, ga) \
    asm volatile("cp.async.cg.shared.global [%0], [%1], 16;" :: "r"(sa), "l"(ga) : "memory")
#define CP_COMMIT() asm volatile("cp.async.commit_group;" ::: "memory")
#define CP_WAIT1()  asm volatile("cp.async.wait_group 1;" ::: "memory")
#define CP_WAIT0()  asm volatile("cp.async.wait_group 0;" ::: "memory")

__device__ __forceinline__ void ldsm_x4(uint32_t* r, uint32_t addr) {
    asm volatile("ldmatrix.sync.aligned.m8n8.x4.shared.b16 {%0,%1,%2,%3}, [%4];"
                 : "=r"(r[0]), "=r"(r[1]), "=r"(r[2]), "=r"(r[3]) : "r"(addr));
}

__device__ __forceinline__ void mma_16816(float* c, const uint32_t* a,
                                          uint32_t b0, uint32_t b1) {
    asm volatile("mma.sync.aligned.m16n8k16.row.col.f32.bf16.bf16.f32 "
                 "{%0,%1,%2,%3}, {%4,%5,%6,%7}, {%8,%9}, {%0,%1,%2,%3};"
                 : "+f"(c[0]), "+f"(c[1]), "+f"(c[2]), "+f"(c[3])
                 : "r"(a[0]), "r"(a[1]), "r"(a[2]), "r"(a[3]), "r"(b0), "r"(b1));
}

// ---------------------------------------------------------------------------
// Triple-block conversion. K=768 per block, K2=3K.
//   A-type (which 0,1): dst = [hi | hi | lo]
//   B-type (which 2,3): dst = [hi | lo | hi]
// Dot over K2: ah*bh + ah*bl + al*bh  (missing al*bl ~ 2^-18 — negligible)
// which: 0=g_xc(from x) 1=g_attc(from g_att) 2=g_wkv(qkv_w rows 768..) 3=g_wprj(proj_w)
// ---------------------------------------------------------------------------
__global__ __launch_bounds__(256) void conv_dual_kernel(
    const float* __restrict__ src_ext, int which, int R, int K, int srow_off)
{
    __nv_bfloat16* dst = (which == 0) ? g_xc : (which == 1) ? g_attc
                       : (which == 2) ? g_wkv : g_wprj;
    const float* src = (which == 1) ? g_att : src_ext;
    const bool atype = (which <= 1);

    size_t total4 = (size_t)R * K / 4;
    size_t idx = (size_t)blockIdx.x * blockDim.x + threadIdx.x;
    if (idx >= total4) return;
    int kq = (int)(idx % (K / 4));
    int r  = (int)(idx / (K / 4));
    float4 v = *(const float4*)(src + (size_t)(srow_off + r) * K + kq * 4);
    __nv_bfloat16 h0 = __float2bfloat16(v.x);
    __nv_bfloat16 h1 = __float2bfloat16(v.y);
    __nv_bfloat16 h2 = __float2bfloat16(v.z);
    __nv_bfloat16 h3 = __float2bfloat16(v.w);
    __nv_bfloat16 l0 = __float2bfloat16(v.x - __bfloat162float(h0));
    __nv_bfloat16 l1 = __float2bfloat16(v.y - __bfloat162float(h1));
    __nv_bfloat16 l2 = __float2bfloat16(v.z - __bfloat162float(h2));
    __nv_bfloat16 l3 = __float2bfloat16(v.w - __bfloat162float(h3));

    __nv_bfloat16* d0 = dst + (size_t)r * K2 + kq * 4;        // block 0: hi
    __nv_bfloat16* d1 = d0 + K;                                // block 1
    __nv_bfloat16* d2 = d0 + 2 * K;                            // block 2
    d0[0] = h0; d0[1] = h1; d0[2] = h2; d0[3] = h3;
    if (atype) {   // [hi | hi | lo]
        d1[0] = h0; d1[1] = h1; d1[2] = h2; d1[3] = h3;
        d2[0] = l0; d2[1] = l1; d2[2] = l2; d2[3] = l3;
    } else {       // [hi | lo | hi]
        d1[0] = l0; d1[1] = l1; d1[2] = l2; d1[3] = l3;
        d2[0] = h0; d2[1] = h1; d2[2] = h2; d2[3] = h3;
    }
}

// ---------------------------------------------------------------------------
// HMMA GEMM over K2=2304: C[m][n] = sum_k A[m][k]*B[n][k] + bias[n]
// 128x128 tile, BK=64 bf16, 256 threads = 8 warps (2m x 4n), warp tile 64x32,
// mma.sync.m16n8k16, SW128-swizzled smem, cp.async double buffering.
// ---------------------------------------------------------------------------
#define GEMM_SMEM 65536

__global__ __launch_bounds__(256) void gemm_mma_kernel(
    int which, const float* __restrict__ bias, float* __restrict__ outp)
{
    extern __shared__ __align__(128) char smem[];
    const uint32_t sb = smem_u32(smem);

    const __nv_bfloat16* __restrict__ A  = which ? g_attc : g_xc;
    const __nv_bfloat16* __restrict__ Bw = which ? g_wprj : g_wkv;
    float* C = which ? outp : g_kv;
    const int N = which ? CDIM : KVW;

    const int tid  = threadIdx.x;
    const int lane = tid & 31;
    const int w    = tid >> 5;
    const int wm   = w >> 2;         // 0..1
    const int wn   = w & 3;          // 0..3
    const int n0   = blockIdx.x * 128;
    const int m0   = blockIdx.y * 128;

    float acc[4][4][4];
#pragma unroll
    for (int mi = 0; mi < 4; mi++)
#pragma unroll
        for (int ni = 0; ni < 4; ni++)
#pragma unroll
            for (int c = 0; c < 4; c++) acc[mi][ni][c] = 0.0f;

    const int srow = tid >> 3;       // base row (0..31), +32 per u
    const int q    = tid & 7;

    auto issue_stage = [&](int ch, int buf) {
        const uint32_t sa_base = sb + (uint32_t)buf * 32768u;
        const uint32_t sb_base = sa_base + 16384u;
#pragma unroll
        for (int u = 0; u < 4; u++) {
            const int row = srow + 32 * u;
            int am = m0 + row; if (am > MROWS - 1) am = MROWS - 1;
            const uint32_t so = SMEM_SWIZZLE_128B((uint32_t)(row * 128 + q * 16));
            CP_ASYNC16(sa_base + so, A  + (size_t)am * K2 + ch * 64 + q * 8);
            CP_ASYNC16(sb_base + so, Bw + (size_t)(n0 + row) * K2 + ch * 64 + q * 8);
        }
        CP_COMMIT();
    };

    const int NSTAGE = K2 / 64;      // 36
    issue_stage(0, 0);

    for (int ch = 0; ch < NSTAGE; ch++) {
        const int buf = ch & 1;
        if (ch + 1 < NSTAGE) { issue_stage(ch + 1, buf ^ 1); CP_WAIT1(); }
        else                 { CP_WAIT0(); }
        __syncthreads();

        const uint32_t abase = sb + (uint32_t)buf * 32768u;
        const uint32_t bbase = abase + 16384u;
        const int rsel = lane & 15;
        const int chi  = lane >> 4;

#pragma unroll
        for (int kk = 0; kk < 4; kk++) {            // four k16 chunks of BK=64
            const int c8 = kk * 2 + chi;            // 16B column chunk
            uint32_t af[4][4], bfr[2][4];
#pragma unroll
            for (int mi = 0; mi < 4; mi++) {
                const int row = wm * 64 + mi * 16 + rsel;
                ldsm_x4(af[mi], abase + SMEM_SWIZZLE_128B((uint32_t)(row * 128 + c8 * 16)));
            }
#pragma unroll
            for (int g = 0; g < 2; g++) {
                const int row = wn * 32 + g * 16 + rsel;
                ldsm_x4(bfr[g], bbase + SMEM_SWIZZLE_128B((uint32_t)(row * 128 + c8 * 16)));
            }
#pragma unroll
            for (int mi = 0; mi < 4; mi++)
#pragma unroll
                for (int ni = 0; ni < 4; ni++) {
                    const int g = ni >> 1, o = ni & 1;
                    mma_16816(acc[mi][ni], af[mi], bfr[g][o], bfr[g][o + 2]);
                }
        }
        __syncthreads();
    }

    // Epilogue: c0,c1 -> (row, col..col+1); c2,c3 -> (row+8, ...)
#pragma unroll
    for (int mi = 0; mi < 4; mi++) {
        const int r0 = m0 + wm * 64 + mi * 16 + (lane >> 2);
        const int r1 = r0 + 8;
#pragma unroll
        for (int ni = 0; ni < 4; ni++) {
            const int col = n0 + wn * 32 + ni * 8 + (lane & 3) * 2;
            const float b0v = bias[col], b1v = bias[col + 1];
            if (r0 < MROWS) {
                float2 v = make_float2(acc[mi][ni][0] + b0v, acc[mi][ni][1] + b1v);
                *(float2*)(C + (size_t)r0 * N + col) = v;
            }
            if (r1 < MROWS) {
                float2 v = make_float2(acc[mi][ni][2] + b0v, acc[mi][ni][3] + b1v);
                *(float2*)(C + (size_t)r1 * N + col) = v;
            }
        }
    }
}

// ---------------------------------------------------------------------------
// Flash-style fused attention (unchanged from round 6 — known good).
// ---------------------------------------------------------------------------
#define ATT_SMEM_FLOATS (64*64 + 3*64*68 + 64)
#define ATT_SMEM_BYTES  (ATT_SMEM_FLOATS * 4)

__global__ __launch_bounds__(256) void attn_kernel()
{
    extern __shared__ float sm[];
    float* Ki_s = sm;
    float* KjT  = Ki_s + 64 * 64;
    float* V_s  = KjT  + 64 * 68;
    float* P_s  = V_s  + 64 * 68;
    float* ftab = P_s  + 64 * 68;

    const int tid = threadIdx.x;
    const int tx = tid & 15;
    const int ty = tid >> 4;
    const int b = blockIdx.y / HEADS, h = blockIdx.y % HEADS;
    const int i0 = blockIdx.x * 64;

    const float* Kp = g_kv + (size_t)b * NSEQ * KVW + h * HD;
    const float* Vp = Kp + CDIM;

    if (tid < 63) {
        float xx = (float)tid - 31.0f;
        ftab[tid] = __expf(-xx * xx * 0.02f);
    }
    {
        const int i  = tid & 63;
        const int d0 = (tid >> 6) * 16;
        int gi = i0 + i; if (gi > NSEQ - 1) gi = NSEQ - 1;
        const float* src = Kp + (size_t)gi * KVW + d0;
#pragma unroll
        for (int g = 0; g < 4; g++)
            *(float4*)&Ki_s[i * 64 + d0 + 4 * g] = *(const float4*)(src + 4 * g);
    }

    int qi1[4], qi2[4]; bool qok[4];
#pragma unroll
    for (int a = 0; a < 4; a++) {
        int i = i0 + ty * 4 + a;
        qok[a] = (i >= 8) && (i < NSEQ);
        qi1[a] = (i - 8) >> 5;
        qi2[a] = (i - 8) & 31;
    }

    float m[4], l[4], O[4][4];
#pragma unroll
    for (int a = 0; a < 4; a++) {
        m[a] = -1e30f; l[a] = 0.0f;
#pragma unroll
        for (int bb = 0; bb < 4; bb++) O[a][bb] = 0.0f;
    }

    const float scale = 0.125f;

    for (int j0 = 0; j0 < NSEQ; j0 += 64) {
        __syncthreads();
        {
            const int j  = tid & 63;
            const int d0 = (tid >> 6) * 16;
            int gj = j0 + j; if (gj > NSEQ - 1) gj = NSEQ - 1;
            const float* kc = Kp + (size_t)gj * KVW + d0;
            const float* vc = Vp + (size_t)gj * KVW + d0;
#pragma unroll
            for (int g = 0; g < 4; g++) {
                float4 k4 = *(const float4*)(kc + 4 * g);
                KjT[(d0 + 4 * g + 0) * 68 + j] = k4.x;
                KjT[(d0 + 4 * g + 1) * 68 + j] = k4.y;
                KjT[(d0 + 4 * g + 2) * 68 + j] = k4.z;
                KjT[(d0 + 4 * g + 3) * 68 + j] = k4.w;
                *(float4*)&V_s[j * 68 + d0 + 4 * g] = *(const float4*)(vc + 4 * g);
            }
        }
        __syncthreads();

        float s[4][4];
#pragma unroll
        for (int a = 0; a < 4; a++)
#pragma unroll
            for (int bb = 0; bb < 4; bb++) s[a][bb] = 0.0f;

#pragma unroll 8
        for (int dd = 0; dd < 64; dd++) {
            float4 kj = *(const float4*)&KjT[dd * 68 + tx * 4];
            float ka0 = Ki_s[(ty * 4 + 0) * 64 + dd];
            float ka1 = Ki_s[(ty * 4 + 1) * 64 + dd];
            float ka2 = Ki_s[(ty * 4 + 2) * 64 + dd];
            float ka3 = Ki_s[(ty * 4 + 3) * 64 + dd];
            s[0][0] += ka0 * kj.x; s[0][1] += ka0 * kj.y; s[0][2] += ka0 * kj.z; s[0][3] += ka0 * kj.w;
            s[1][0] += ka1 * kj.x; s[1][1] += ka1 * kj.y; s[1][2] += ka1 * kj.z; s[1][3] += ka1 * kj.w;
            s[2][0] += ka2 * kj.x; s[2][1] += ka2 * kj.y; s[2][2] += ka2 * kj.z; s[2][3] += ka2 * kj.w;
            s[3][0] += ka3 * kj.x; s[3][1] += ka3 * kj.y; s[3][2] += ka3 * kj.z; s[3][3] += ka3 * kj.w;
        }

#pragma unroll
        for (int bb = 0; bb < 4; bb++) {
            int j = j0 + tx * 4 + bb;
            bool jin = (j < NSEQ);
            bool jbias = jin && (j >= 8);
            int kj1 = (j - 8) >> 5, kj2 = (j - 8) & 31;
#pragma unroll
            for (int a = 0; a < 4; a++) {
                float val = s[a][bb] * scale;
                if (jbias && qok[a])
                    val += ftab[qi1[a] - kj1 + 31] * ftab[qi2[a] - kj2 + 31];
                if (!jin) val = -1e30f;
                s[a][bb] = val;
            }
        }

#pragma unroll
        for (int a = 0; a < 4; a++) {
            float tm = fmaxf(fmaxf(s[a][0], s[a][1]), fmaxf(s[a][2], s[a][3]));
#pragma unroll
            for (int o = 8; o; o >>= 1)
                tm = fmaxf(tm, __shfl_xor_sync(0xffffffffu, tm, o, 16));
            float mn = fmaxf(m[a], tm);
            float c = __expf(m[a] - mn);
            float e0 = __expf(s[a][0] - mn);
            float e1 = __expf(s[a][1] - mn);
            float e2 = __expf(s[a][2] - mn);
            float e3 = __expf(s[a][3] - mn);
            float rs = e0 + e1 + e2 + e3;
#pragma unroll
            for (int o = 8; o; o >>= 1)
                rs += __shfl_xor_sync(0xffffffffu, rs, o, 16);
            l[a] = l[a] * c + rs;
            m[a] = mn;
            O[a][0] *= c; O[a][1] *= c; O[a][2] *= c; O[a][3] *= c;
            *(float4*)&P_s[(ty * 4 + a) * 68 + tx * 4] = make_float4(e0, e1, e2, e3);
        }
        __syncthreads();

#pragma unroll 8
        for (int jj = 0; jj < 64; jj++) {
            float4 v = *(const float4*)&V_s[jj * 68 + tx * 4];
            float p0 = P_s[(ty * 4 + 0) * 68 + jj];
            float p1 = P_s[(ty * 4 + 1) * 68 + jj];
            float p2 = P_s[(ty * 4 + 2) * 68 + jj];
            float p3 = P_s[(ty * 4 + 3) * 68 + jj];
            O[0][0] += p0 * v.x; O[0][1] += p0 * v.y; O[0][2] += p0 * v.z; O[0][3] += p0 * v.w;
            O[1][0] += p1 * v.x; O[1][1] += p1 * v.y; O[1][2] += p1 * v.z; O[1][3] += p1 * v.w;
            O[2][0] += p2 * v.x; O[2][1] += p2 * v.y; O[2][2] += p2 * v.z; O[2][3] += p2 * v.w;
            O[3][0] += p3 * v.x; O[3][1] += p3 * v.y; O[3][2] += p3 * v.z; O[3][3] += p3 * v.w;
        }
    }

#pragma unroll
    for (int a = 0; a < 4; a++) {
        int i = i0 + ty * 4 + a;
        if (i < NSEQ) {
            float inv = 1.0f / l[a];
            float4 o = make_float4(O[a][0] * inv, O[a][1] * inv,
                                   O[a][2] * inv, O[a][3] * inv);
            *(float4*)(g_att + (size_t)(b * NSEQ + i) * CDIM + h * HD + tx * 4) = o;
        }
    }
}

// ---------------------------------------------------------------------------
extern "C" void kernel_launch(void* const* d_in, const int* in_sizes, int n_in,
                              void* d_out, int out_size)
{
    const float* x = nullptr;
    const float* qkv_w = nullptr;
    const float* qkv_b = nullptr;
    const float* proj_w = nullptr;
    const float* proj_b = nullptr;
    for (int i = 0; i < n_in; i++) {
        switch (in_sizes[i]) {
            case 6340608: x      = (const float*)d_in[i]; break;
            case 1769472: qkv_w  = (const float*)d_in[i]; break;
            case 2304:    qkv_b  = (const float*)d_in[i]; break;
            case 589824:  proj_w = (const float*)d_in[i]; break;
            case 768:     proj_b = (const float*)d_in[i]; break;
        }
    }
    float* out = (float*)d_out;

    cudaFuncSetAttribute(attn_kernel, cudaFuncAttributeMaxDynamicSharedMemorySize, ATT_SMEM_BYTES);
    cudaFuncSetAttribute(gemm_mma_kernel, cudaFuncAttributeMaxDynamicSharedMemorySize, GEMM_SMEM);

    // conversions: x, W_kv, W_proj -> triple-block bf16
    {
        size_t t4 = (size_t)MROWS * CDIM / 4;
        conv_dual_kernel<<<(unsigned)((t4 + 255) / 256), 256>>>(x, 0, MROWS, CDIM, 0);
        t4 = (size_t)KVW * CDIM / 4;
        conv_dual_kernel<<<(unsigned)((t4 + 255) / 256), 256>>>(qkv_w, 2, KVW, CDIM, CDIM);
        t4 = (size_t)CDIM * CDIM / 4;
        conv_dual_kernel<<<(unsigned)((t4 + 255) / 256), 256>>>(proj_w, 3, CDIM, CDIM, 0);
    }
    // 1) K,V projection via HMMA -> g_kv (fp32)
    {
        dim3 grid(KVW / 128, (MROWS + 127) / 128);   // 12 x 65
        gemm_mma_kernel<<<grid, 256, GEMM_SMEM>>>(0, qkv_b + CDIM, nullptr);
    }
    // 2) flash attention -> g_att
    {
        dim3 grid((NSEQ + 63) / 64, BATCH * HEADS);  // 17 x 96
        attn_kernel<<<grid, 256, ATT_SMEM_BYTES>>>();
    }
    // 3) convert attn output, then output projection via HMMA -> d_out
    {
        size_t t4 = (size_t)MROWS * CDIM / 4;
        conv_dual_kernel<<<(unsigned)((t4 + 255) / 256), 256>>>(nullptr, 1, MROWS, CDIM, 0);
        dim3 grid(CDIM / 128, (MROWS + 127) / 128);  // 6 x 65
        gemm_mma_kernel<<<grid, 256, GEMM_SMEM>>>(1, proj_b, out);
    }
}

// round 10
// speedup vs baseline: 5.4761x; 1.7704x over previous
#include <cuda_runtime.h>
#include <cuda_bf16.h>
#include <cstdint>
#include <cstddef>

// Problem constants
#define BATCH 8
#define NSEQ  1032          // 32*32 + 8
#define NSEQP 1088          // padded to 17*64
#define CDIM  768
#define HEADS 12
#define HD    64
#define MROWS (BATCH*NSEQ)  // 8256
#define KVW   1536          // k+v columns
#define K2    2304          // triple-block K (3*768): A=[hi|hi|lo], B=[hi|lo|hi]
#define NPANEL (BATCH*HEADS) // 96

// Device scratch (static globals — zero-initialized, no runtime allocation).
__device__ float g_kv[(size_t)MROWS * KVW];          // K|V fp32
__device__ float g_att[(size_t)MROWS * CDIM];        // attention output fp32
__device__ __nv_bfloat16 g_xc  [(size_t)MROWS * K2]; // x       A-type [hi|hi|lo]
__device__ __nv_bfloat16 g_attc[(size_t)MROWS * K2]; // attnout A-type [hi|hi|lo]
__device__ __nv_bfloat16 g_wkv [(size_t)KVW   * K2]; // qkv_w rows 768.. B-type [hi|lo|hi]
__device__ __nv_bfloat16 g_wprj[(size_t)CDIM  * K2]; // proj_w B-type [hi|lo|hi]
__device__ __nv_bfloat16 g_kc[(size_t)NPANEL * NSEQP * 128];    // per (b,h): [j][K_hi(64)|K_lo(64)]
__device__ __nv_bfloat16 g_vt[(size_t)NPANEL * 64 * 2 * NSEQP]; // per (b,h): [d][Vt_hi(NSEQP)|Vt_lo(NSEQP)]

// ---------------------------------------------------------------------------
// Helpers (portable PTX: ldmatrix / mma.sync / cp.async)
// ---------------------------------------------------------------------------
__device__ __forceinline__ uint32_t smem_u32(const void* p) {
    uint32_t a;
    asm("{ .reg .u64 t; cvta.to.shared.u64 t, %1; cvt.u32.u64 %0, t; }" : "=r"(a) : "l"(p));
    return a;
}
#define SMEM_SWIZZLE_128B(x) ((x) ^ (((x) >> 3) & 0x70))

#define CP_ASYNC16(sa, ga) \
    asm volatile("cp.async.cg.shared.global [%0], [%1], 16;" :: "r"(sa), "l"(ga) : "memory")
#define CP_COMMIT() asm volatile("cp.async.commit_group;" ::: "memory")
#define CP_WAIT1()  asm volatile("cp.async.wait_group 1;" ::: "memory")
#define CP_WAIT0()  asm volatile("cp.async.wait_group 0;" ::: "memory")

__device__ __forceinline__ void ldsm_x4(uint32_t* r, uint32_t addr) {
    asm volatile("ldmatrix.sync.aligned.m8n8.x4.shared.b16 {%0,%1,%2,%3}, [%4];"
                 : "=r"(r[0]), "=r"(r[1]), "=r"(r[2]), "=r"(r[3]) : "r"(addr));
}

__device__ __forceinline__ void mma_16816(float* c, const uint32_t* a,
                                          uint32_t b0, uint32_t b1) {
    asm volatile("mma.sync.aligned.m16n8k16.row.col.f32.bf16.bf16.f32 "
                 "{%0,%1,%2,%3}, {%4,%5,%6,%7}, {%8,%9}, {%0,%1,%2,%3};"
                 : "+f"(c[0]), "+f"(c[1]), "+f"(c[2]), "+f"(c[3])
                 : "r"(a[0]), "r"(a[1]), "r"(a[2]), "r"(a[3]), "r"(b0), "r"(b1));
}

// ---------------------------------------------------------------------------
// Triple-block conversion for projection GEMMs (unchanged, verified R9).
// ---------------------------------------------------------------------------
__global__ __launch_bounds__(256) void conv_dual_kernel(
    const float* __restrict__ src_ext, int which, int R, int K, int srow_off)
{
    __nv_bfloat16* dst = (which == 0) ? g_xc : (which == 1) ? g_attc
                       : (which == 2) ? g_wkv : g_wprj;
    const float* src = (which == 1) ? g_att : src_ext;
    const bool atype = (which <= 1);

    size_t total4 = (size_t)R * K / 4;
    size_t idx = (size_t)blockIdx.x * blockDim.x + threadIdx.x;
    if (idx >= total4) return;
    int kq = (int)(idx % (K / 4));
    int r  = (int)(idx / (K / 4));
    float4 v = *(const float4*)(src + (size_t)(srow_off + r) * K + kq * 4);
    __nv_bfloat16 h0 = __float2bfloat16(v.x);
    __nv_bfloat16 h1 = __float2bfloat16(v.y);
    __nv_bfloat16 h2 = __float2bfloat16(v.z);
    __nv_bfloat16 h3 = __float2bfloat16(v.w);
    __nv_bfloat16 l0 = __float2bfloat16(v.x - __bfloat162float(h0));
    __nv_bfloat16 l1 = __float2bfloat16(v.y - __bfloat162float(h1));
    __nv_bfloat16 l2 = __float2bfloat16(v.z - __bfloat162float(h2));
    __nv_bfloat16 l3 = __float2bfloat16(v.w - __bfloat162float(h3));

    __nv_bfloat16* d0 = dst + (size_t)r * K2 + kq * 4;
    __nv_bfloat16* d1 = d0 + K;
    __nv_bfloat16* d2 = d0 + 2 * K;
    d0[0] = h0; d0[1] = h1; d0[2] = h2; d0[3] = h3;
    if (atype) {
        d1[0] = h0; d1[1] = h1; d1[2] = h2; d1[3] = h3;
        d2[0] = l0; d2[1] = l1; d2[2] = l2; d2[3] = l3;
    } else {
        d1[0] = l0; d1[1] = l1; d1[2] = l2; d1[3] = l3;
        d2[0] = h0; d2[1] = h1; d2[2] = h2; d2[3] = h3;
    }
}

// ---------------------------------------------------------------------------
// K/V panel conversion for attn: g_kv fp32 -> g_kc (K hi|lo) + g_vt (V^T hi|lo)
// One block per (j-tile, panel). V transposed through smem for coalesced writes.
// ---------------------------------------------------------------------------
__global__ __launch_bounds__(256) void conv_kv_kernel()
{
    __shared__ float vt[64][65];
    const int tid = threadIdx.x;
    const int bh = blockIdx.y, b = bh / HEADS, h = bh % HEADS;
    const int j0 = blockIdx.x * 64;

#pragma unroll
    for (int it = 0; it < 16; it++) {
        int idx = tid + 256 * it;
        int j = idx >> 6, d = idx & 63;
        int gj = j0 + j;
        float vvv = 0.0f;
        if (gj < NSEQ) {
            const float* src = g_kv + ((size_t)b * NSEQ + gj) * KVW + h * HD;
            float kvv = src[d];
            vvv = src[CDIM + d];
            __nv_bfloat16 hi = __float2bfloat16(kvv);
            __nv_bfloat16 lo = __float2bfloat16(kvv - __bfloat162float(hi));
            __nv_bfloat16* dst = g_kc + ((size_t)bh * NSEQP + gj) * 128;
            dst[d] = hi; dst[64 + d] = lo;
        }
        vt[j][d] = vvv;
    }
    __syncthreads();
#pragma unroll
    for (int it = 0; it < 16; it++) {
        int idx = tid + 256 * it;
        int d = idx >> 6, j = idx & 63;
        int gj = j0 + j;
        if (gj < NSEQ) {
            float v = vt[j][d];
            __nv_bfloat16 hi = __float2bfloat16(v);
            __nv_bfloat16 lo = __float2bfloat16(v - __bfloat162float(hi));
            __nv_bfloat16* dst = g_vt + ((size_t)bh * 64 + d) * (2 * NSEQP);
            dst[gj] = hi; dst[NSEQP + gj] = lo;
        }
    }
}

// ---------------------------------------------------------------------------
// HMMA GEMM over K2=2304 (unchanged, verified R9).
// ---------------------------------------------------------------------------
#define GEMM_SMEM 65536

__global__ __launch_bounds__(256) void gemm_mma_kernel(
    int which, const float* __restrict__ bias, float* __restrict__ outp)
{
    extern __shared__ __align__(128) char smem[];
    const uint32_t sb = smem_u32(smem);

    const __nv_bfloat16* __restrict__ A  = which ? g_attc : g_xc;
    const __nv_bfloat16* __restrict__ Bw = which ? g_wprj : g_wkv;
    float* C = which ? outp : g_kv;
    const int N = which ? CDIM : KVW;

    const int tid  = threadIdx.x;
    const int lane = tid & 31;
    const int w    = tid >> 5;
    const int wm   = w >> 2;
    const int wn   = w & 3;
    const int n0   = blockIdx.x * 128;
    const int m0   = blockIdx.y * 128;

    float acc[4][4][4];
#pragma unroll
    for (int mi = 0; mi < 4; mi++)
#pragma unroll
        for (int ni = 0; ni < 4; ni++)
#pragma unroll
            for (int c = 0; c < 4; c++) acc[mi][ni][c] = 0.0f;

    const int srow = tid >> 3;
    const int q    = tid & 7;

    auto issue_stage = [&](int ch, int buf) {
        const uint32_t sa_base = sb + (uint32_t)buf * 32768u;
        const uint32_t sb_base = sa_base + 16384u;
#pragma unroll
        for (int u = 0; u < 4; u++) {
            const int row = srow + 32 * u;
            int am = m0 + row; if (am > MROWS - 1) am = MROWS - 1;
            const uint32_t so = SMEM_SWIZZLE_128B((uint32_t)(row * 128 + q * 16));
            CP_ASYNC16(sa_base + so, A  + (size_t)am * K2 + ch * 64 + q * 8);
            CP_ASYNC16(sb_base + so, Bw + (size_t)(n0 + row) * K2 + ch * 64 + q * 8);
        }
        CP_COMMIT();
    };

    const int NSTAGE = K2 / 64;      // 36
    issue_stage(0, 0);

    for (int ch = 0; ch < NSTAGE; ch++) {
        const int buf = ch & 1;
        if (ch + 1 < NSTAGE) { issue_stage(ch + 1, buf ^ 1); CP_WAIT1(); }
        else                 { CP_WAIT0(); }
        __syncthreads();

        const uint32_t abase = sb + (uint32_t)buf * 32768u;
        const uint32_t bbase = abase + 16384u;
        const int rsel = lane & 15;
        const int chi  = lane >> 4;

#pragma unroll
        for (int kk = 0; kk < 4; kk++) {
            const int c8 = kk * 2 + chi;
            uint32_t af[4][4], bfr[2][4];
#pragma unroll
            for (int mi = 0; mi < 4; mi++) {
                const int row = wm * 64 + mi * 16 + rsel;
                ldsm_x4(af[mi], abase + SMEM_SWIZZLE_128B((uint32_t)(row * 128 + c8 * 16)));
            }
#pragma unroll
            for (int g = 0; g < 2; g++) {
                const int row = wn * 32 + g * 16 + rsel;
                ldsm_x4(bfr[g], bbase + SMEM_SWIZZLE_128B((uint32_t)(row * 128 + c8 * 16)));
            }
#pragma unroll
            for (int mi = 0; mi < 4; mi++)
#pragma unroll
                for (int ni = 0; ni < 4; ni++) {
                    const int g = ni >> 1, o = ni & 1;
                    mma_16816(acc[mi][ni], af[mi], bfr[g][o], bfr[g][o + 2]);
                }
        }
        __syncthreads();
    }

#pragma unroll
    for (int mi = 0; mi < 4; mi++) {
        const int r0 = m0 + wm * 64 + mi * 16 + (lane >> 2);
        const int r1 = r0 + 8;
#pragma unroll
        for (int ni = 0; ni < 4; ni++) {
            const int col = n0 + wn * 32 + ni * 8 + (lane & 3) * 2;
            const float b0v = bias[col], b1v = bias[col + 1];
            if (r0 < MROWS) {
                float2 v = make_float2(acc[mi][ni][0] + b0v, acc[mi][ni][1] + b1v);
                *(float2*)(C + (size_t)r0 * N + col) = v;
            }
            if (r1 < MROWS) {
                float2 v = make_float2(acc[mi][ni][2] + b0v, acc[mi][ni][3] + b1v);
                *(float2*)(C + (size_t)r1 * N + col) = v;
            }
        }
    }
}

// ---------------------------------------------------------------------------
// Tensor-core flash attention.
// CTA = (b,h) x 128 i-rows, 8 warps x (16 rows x 64 cols).
// Triple-block HMMA for S = Ki.Kj^T and O += P.V; online softmax on fragments.
// ---------------------------------------------------------------------------
#define AK_KI_HI 0
#define AK_KI_LO 16384
#define AK_KJ_HI 32768
#define AK_KJ_LO 40960
#define AK_VT_HI 49152
#define AK_VT_LO 57344
#define AK_P_HI  65536
#define AK_P_LO  81920
#define AK_FTAB  98304
#define AK_SMEM  (98304 + 256)

__global__ __launch_bounds__(256) void attn_mma_kernel()
{
    extern __shared__ __align__(128) char sm[];
    const uint32_t sb = smem_u32(sm);
    float* ftab = (float*)(sm + AK_FTAB);

    const int tid = threadIdx.x, lane = tid & 31, w = tid >> 5;
    const int bh = blockIdx.y, b = bh / HEADS, h = bh % HEADS;
    const int i0 = blockIdx.x * 128;

    if (tid < 63) { float xx = (float)tid - 31.0f; ftab[tid] = __expf(-xx * xx * 0.02f); }

    // Ki tiles (hi/lo), loaded once
    {
        const int srow = tid >> 3, q = tid & 7;
#pragma unroll
        for (int u = 0; u < 4; u++) {
            int row = srow + 32 * u;
            int gi = i0 + row; if (gi > NSEQ - 1) gi = NSEQ - 1;
            const __nv_bfloat16* src = g_kc + ((size_t)bh * NSEQP + gi) * 128 + q * 8;
            uint32_t so = SMEM_SWIZZLE_128B((uint32_t)(row * 128 + q * 16));
            CP_ASYNC16(sb + AK_KI_HI + so, src);
            CP_ASYNC16(sb + AK_KI_LO + so, src + 64);
        }
        CP_COMMIT();
    }

    const int rsel = lane & 15, chi = lane >> 4;
    const int rA = w * 16 + (lane >> 2);      // local row for c0,c1
    const int iA = i0 + rA, iB = iA + 8;
    const bool okA = (iA >= 8) && (iA < NSEQ);
    const bool okB = (iB >= 8) && (iB < NSEQ);
    const int qiA1 = (iA - 8) >> 5, qiA2 = (iA - 8) & 31;
    const int qiB1 = (iB - 8) >> 5, qiB2 = (iB - 8) & 31;

    float mA = -1e30f, mB = -1e30f, lA = 0.0f, lB = 0.0f;
    float O[8][4];
#pragma unroll
    for (int ni = 0; ni < 8; ni++)
#pragma unroll
        for (int c = 0; c < 4; c++) O[ni][c] = 0.0f;

    const float scale = 0.125f;

    for (int jt = 0; jt < NSEQP; jt += 64) {
        __syncthreads();   // prior tile fully consumed by all warps
        {
            const int srow = tid >> 3, q = tid & 7;
#pragma unroll
            for (int u = 0; u < 2; u++) {
                int row = srow + 32 * u;
                const __nv_bfloat16* sk = g_kc + ((size_t)bh * NSEQP + jt + row) * 128 + q * 8;
                const __nv_bfloat16* sv = g_vt + ((size_t)bh * 64 + row) * (2 * NSEQP) + jt + q * 8;
                uint32_t so = SMEM_SWIZZLE_128B((uint32_t)(row * 128 + q * 16));
                CP_ASYNC16(sb + AK_KJ_HI + so, sk);
                CP_ASYNC16(sb + AK_KJ_LO + so, sk + 64);
                CP_ASYNC16(sb + AK_VT_HI + so, sv);
                CP_ASYNC16(sb + AK_VT_LO + so, sv + NSEQP);
            }
            CP_COMMIT(); CP_WAIT0();
        }
        __syncthreads();

        // ---- S = Ki.Kj^T: passes (hi,hi),(hi,lo),(lo,hi) ----
        float s[8][4];
#pragma unroll
        for (int ni = 0; ni < 8; ni++)
#pragma unroll
            for (int c = 0; c < 4; c++) s[ni][c] = 0.0f;

        const uint32_t apass[3] = {AK_KI_HI, AK_KI_HI, AK_KI_LO};
        const uint32_t bpass[3] = {AK_KJ_HI, AK_KJ_LO, AK_KJ_HI};
#pragma unroll
        for (int ps = 0; ps < 3; ps++) {
#pragma unroll
            for (int kk = 0; kk < 4; kk++) {
                const int c8 = kk * 2 + chi;
                uint32_t af[4], bfr[4][4];
                ldsm_x4(af, sb + apass[ps] +
                        SMEM_SWIZZLE_128B((uint32_t)((w * 16 + rsel) * 128 + c8 * 16)));
#pragma unroll
                for (int g = 0; g < 4; g++)
                    ldsm_x4(bfr[g], sb + bpass[ps] +
                            SMEM_SWIZZLE_128B((uint32_t)((g * 16 + rsel) * 128 + c8 * 16)));
#pragma unroll
                for (int ni = 0; ni < 8; ni++)
                    mma_16816(s[ni], af, bfr[ni >> 1][ni & 1], bfr[ni >> 1][(ni & 1) + 2]);
            }
        }

        // ---- scale + gaussian bias + tail mask ----
#pragma unroll
        for (int ni = 0; ni < 8; ni++) {
            const int jbase = jt + ni * 8 + ((lane & 3) << 1);
#pragma unroll
            for (int c = 0; c < 4; c++) {
                const int j = jbase + (c & 1);
                float val = s[ni][c] * scale;
                const bool ok = (c < 2) ? okA : okB;
                const int q1 = (c < 2) ? qiA1 : qiB1;
                const int q2 = (c < 2) ? qiA2 : qiB2;
                if (j < NSEQ) {
                    if (ok && j >= 8)
                        val += ftab[q1 - ((j - 8) >> 5) + 31] * ftab[q2 - ((j - 8) & 31) + 31];
                } else val = -1e30f;
                s[ni][c] = val;
            }
        }

        // ---- online softmax (rows rA via c0,c1 and rA+8 via c2,c3) ----
        float tA = -1e30f, tB = -1e30f;
#pragma unroll
        for (int ni = 0; ni < 8; ni++) {
            tA = fmaxf(tA, fmaxf(s[ni][0], s[ni][1]));
            tB = fmaxf(tB, fmaxf(s[ni][2], s[ni][3]));
        }
        tA = fmaxf(tA, __shfl_xor_sync(0xffffffffu, tA, 1));
        tA = fmaxf(tA, __shfl_xor_sync(0xffffffffu, tA, 2));
        tB = fmaxf(tB, __shfl_xor_sync(0xffffffffu, tB, 1));
        tB = fmaxf(tB, __shfl_xor_sync(0xffffffffu, tB, 2));
        const float mnA = fmaxf(mA, tA), mnB = fmaxf(mB, tB);
        const float cA = __expf(mA - mnA), cB = __expf(mB - mnB);
        float rsA = 0.0f, rsB = 0.0f;
#pragma unroll
        for (int ni = 0; ni < 8; ni++) {
            s[ni][0] = __expf(s[ni][0] - mnA); rsA += s[ni][0];
            s[ni][1] = __expf(s[ni][1] - mnA); rsA += s[ni][1];
            s[ni][2] = __expf(s[ni][2] - mnB); rsB += s[ni][2];
            s[ni][3] = __expf(s[ni][3] - mnB); rsB += s[ni][3];
        }
        rsA += __shfl_xor_sync(0xffffffffu, rsA, 1);
        rsA += __shfl_xor_sync(0xffffffffu, rsA, 2);
        rsB += __shfl_xor_sync(0xffffffffu, rsB, 1);
        rsB += __shfl_xor_sync(0xffffffffu, rsB, 2);
        lA = lA * cA + rsA; lB = lB * cB + rsB;
        mA = mnA; mB = mnB;

        // ---- P -> smem (hi/lo, warp-private rows) + O rescale ----
        const uint32_t rowoffA = (uint32_t)((w * 16 + (lane >> 2)) * 128 + (lane & 3) * 4);
        const uint32_t rowoffB = rowoffA + 8 * 128;
#pragma unroll
        for (int ni = 0; ni < 8; ni++) {
            O[ni][0] *= cA; O[ni][1] *= cA; O[ni][2] *= cB; O[ni][3] *= cB;

            __nv_bfloat16 h0 = __float2bfloat16(s[ni][0]);
            __nv_bfloat16 h1 = __float2bfloat16(s[ni][1]);
            __nv_bfloat162 hv; hv.x = h0; hv.y = h1;
            __nv_bfloat162 lv;
            lv.x = __float2bfloat16(s[ni][0] - __bfloat162float(h0));
            lv.y = __float2bfloat16(s[ni][1] - __bfloat162float(h1));
            const uint32_t offA = SMEM_SWIZZLE_128B(rowoffA + ni * 16);
            *(__nv_bfloat162*)(sm + AK_P_HI + offA) = hv;
            *(__nv_bfloat162*)(sm + AK_P_LO + offA) = lv;

            __nv_bfloat16 h2 = __float2bfloat16(s[ni][2]);
            __nv_bfloat16 h3 = __float2bfloat16(s[ni][3]);
            __nv_bfloat162 hv2; hv2.x = h2; hv2.y = h3;
            __nv_bfloat162 lv2;
            lv2.x = __float2bfloat16(s[ni][2] - __bfloat162float(h2));
            lv2.y = __float2bfloat16(s[ni][3] - __bfloat162float(h3));
            const uint32_t offB = SMEM_SWIZZLE_128B(rowoffB + ni * 16);
            *(__nv_bfloat162*)(sm + AK_P_HI + offB) = hv2;
            *(__nv_bfloat162*)(sm + AK_P_LO + offB) = lv2;
        }
        __syncwarp();

        // ---- O += P.V: passes (P_hi,V_hi),(P_hi,V_lo),(P_lo,V_hi) ----
        const uint32_t papass[3] = {AK_P_HI, AK_P_HI, AK_P_LO};
        const uint32_t vbpass[3] = {AK_VT_HI, AK_VT_LO, AK_VT_HI};
#pragma unroll
        for (int ps = 0; ps < 3; ps++) {
#pragma unroll
            for (int kk = 0; kk < 4; kk++) {
                const int c8 = kk * 2 + chi;
                uint32_t af[4], bfr[4][4];
                ldsm_x4(af, sb + papass[ps] +
                        SMEM_SWIZZLE_128B((uint32_t)((w * 16 + rsel) * 128 + c8 * 16)));
#pragma unroll
                for (int g = 0; g < 4; g++)
                    ldsm_x4(bfr[g], sb + vbpass[ps] +
                            SMEM_SWIZZLE_128B((uint32_t)((g * 16 + rsel) * 128 + c8 * 16)));
#pragma unroll
                for (int ni = 0; ni < 8; ni++)
                    mma_16816(O[ni], af, bfr[ni >> 1][ni & 1], bfr[ni >> 1][(ni & 1) + 2]);
            }
        }
    }

    // ---- epilogue: normalize, write ----
    const float invA = 1.0f / lA, invB = 1.0f / lB;
#pragma unroll
    for (int ni = 0; ni < 8; ni++) {
        const int d = ni * 8 + ((lane & 3) << 1);
        if (iA < NSEQ) {
            float2 v = make_float2(O[ni][0] * invA, O[ni][1] * invA);
            *(float2*)(g_att + ((size_t)(b * NSEQ + iA)) * CDIM + h * HD + d) = v;
        }
        if (iB < NSEQ) {
            float2 v = make_float2(O[ni][2] * invB, O[ni][3] * invB);
            *(float2*)(g_att + ((size_t)(b * NSEQ + iB)) * CDIM + h * HD + d) = v;
        }
    }
}

// ---------------------------------------------------------------------------
extern "C" void kernel_launch(void* const* d_in, const int* in_sizes, int n_in,
                              void* d_out, int out_size)
{
    const float* x = nullptr;
    const float* qkv_w = nullptr;
    const float* qkv_b = nullptr;
    const float* proj_w = nullptr;
    const float* proj_b = nullptr;
    for (int i = 0; i < n_in; i++) {
        switch (in_sizes[i]) {
            case 6340608: x      = (const float*)d_in[i]; break;
            case 1769472: qkv_w  = (const float*)d_in[i]; break;
            case 2304:    qkv_b  = (const float*)d_in[i]; break;
            case 589824:  proj_w = (const float*)d_in[i]; break;
            case 768:     proj_b = (const float*)d_in[i]; break;
        }
    }
    float* out = (float*)d_out;

    cudaFuncSetAttribute(gemm_mma_kernel, cudaFuncAttributeMaxDynamicSharedMemorySize, GEMM_SMEM);
    cudaFuncSetAttribute(attn_mma_kernel, cudaFuncAttributeMaxDynamicSharedMemorySize, AK_SMEM);

    // conversions: x, W_kv, W_proj -> triple-block bf16
    {
        size_t t4 = (size_t)MROWS * CDIM / 4;
        conv_dual_kernel<<<(unsigned)((t4 + 255) / 256), 256>>>(x, 0, MROWS, CDIM, 0);
        t4 = (size_t)KVW * CDIM / 4;
        conv_dual_kernel<<<(unsigned)((t4 + 255) / 256), 256>>>(qkv_w, 2, KVW, CDIM, CDIM);
        t4 = (size_t)CDIM * CDIM / 4;
        conv_dual_kernel<<<(unsigned)((t4 + 255) / 256), 256>>>(proj_w, 3, CDIM, CDIM, 0);
    }
    // 1) K,V projection via HMMA -> g_kv (fp32)
    {
        dim3 grid(KVW / 128, (MROWS + 127) / 128);   // 12 x 65
        gemm_mma_kernel<<<grid, 256, GEMM_SMEM>>>(0, qkv_b + CDIM, nullptr);
    }
    // 2) K/V panel conversion (hi/lo bf16, V transposed)
    {
        dim3 grid(17, NPANEL);                       // 17 x 96
        conv_kv_kernel<<<grid, 256>>>();
    }
    // 3) tensor-core flash attention -> g_att
    {
        dim3 grid((NSEQ + 127) / 128, NPANEL);       // 9 x 96
        attn_mma_kernel<<<grid, 256, AK_SMEM>>>();
    }
    // 4) convert attn output, then output projection via HMMA -> d_out
    {
        size_t t4 = (size_t)MROWS * CDIM / 4;
        conv_dual_kernel<<<(unsigned)((t4 + 255) / 256), 256>>>(nullptr, 1, MROWS, CDIM, 0);
        dim3 grid(CDIM / 128, (MROWS + 127) / 128);  // 6 x 65
        gemm_mma_kernel<<<grid, 256, GEMM_SMEM>>>(1, proj_b, out);
    }
}